// round 6
// baseline (speedup 1.0000x reference)
#include <cuda_runtime.h>
#include <cstdint>

// Problem constants
#define BATCH    8
#define N_NODES  8192
#define CH       128
#define NEXP     64
#define NODES_PER_CHUNK 16
#define MAX_PAD  9216
#define MAX_CHK  576

#define KT        32
#define ROW_BYTES 144                      // 32 tf32 + 16B pad -> conflict-free ldmatrix
#define STAGE     (2 * 128 * ROW_BYTES)    // 36864: A tile + B tile
#define NSTAGES   3
#define SMEM_NODE (NSTAGES * STAGE)        // 110592
#define SMEM_TOTAL (SMEM_NODE + 64)

// Scratch (device globals; re-initialized every run by K_pre)
__device__ int   g_sorted[MAX_PAD];
__device__ int   g_chunk_expert[MAX_CHK];
__device__ int   g_hist[NEXP];
__device__ int   g_cnt[NEXP];
__device__ int   g_is64;
__device__ float g_Wr[NEXP * CH * CH];     // tf32-rounded W

// ---------------------------------------------------------------------------
// helpers
// ---------------------------------------------------------------------------
__device__ __forceinline__ uint32_t smem_u32(const void* p) {
    uint32_t a;
    asm("{ .reg .u64 t; cvta.to.shared.u64 t, %1; cvt.u32.u64 %0, t; }"
        : "=r"(a) : "l"(p));
    return a;
}

__device__ __forceinline__ unsigned f2tf32(float f) {
    unsigned u;
    asm("cvt.rna.tf32.f32 %0, %1;" : "=r"(u) : "f"(f));
    return u;
}

__device__ __forceinline__ void cp16(uint32_t dst, const void* src, int sz) {
    asm volatile("cp.async.cg.shared.global [%0], [%1], 16, %2;"
                 :: "r"(dst), "l"(src), "r"(sz) : "memory");
}
__device__ __forceinline__ void cp_commit() {
    asm volatile("cp.async.commit_group;" ::: "memory");
}
template <int N>
__device__ __forceinline__ void cp_wait() {
    asm volatile("cp.async.wait_group %0;" :: "n"(N) : "memory");
}

__device__ __forceinline__ void ldsm_x4(uint32_t* r, uint32_t addr) {
    asm volatile("ldmatrix.sync.aligned.m8n8.x4.shared.b16 {%0,%1,%2,%3}, [%4];"
                 : "=r"(r[0]), "=r"(r[1]), "=r"(r[2]), "=r"(r[3])
                 : "r"(addr));
}

__device__ __forceinline__ void mma_tf32(float* d, const uint32_t* a, const uint32_t* b) {
    asm volatile(
        "mma.sync.aligned.m16n8k8.row.col.f32.tf32.tf32.f32 "
        "{%0,%1,%2,%3}, {%4,%5,%6,%7}, {%8,%9}, {%0,%1,%2,%3};\n"
        : "+f"(d[0]), "+f"(d[1]), "+f"(d[2]), "+f"(d[3])
        : "r"(a[0]), "r"(a[1]), "r"(a[2]), "r"(a[3]),
          "r"(b[0]), "r"(b[1]));
}

// ---------------------------------------------------------------------------
// K_pre (128 CTAs x 256): round W to tf32, init scratch, detect sel dtype.
// Only CTA 0 writes g_is64 (no cross-CTA race; no reliance on initial zeros).
// ---------------------------------------------------------------------------
__global__ void pre_kernel(const float* __restrict__ W,
                           const long long* __restrict__ sel64) {
    const int tid = threadIdx.x;
    const int bid = blockIdx.x;

    // W rounding: 262144 float4 total, 2048 per CTA, 8 per thread
#pragma unroll
    for (int j = 0; j < 8; j++) {
        int i = bid * 2048 + j * 256 + tid;
        float4 v = ((const float4*)W)[i];
        uint4 t;
        t.x = f2tf32(v.x); t.y = f2tf32(v.y);
        t.z = f2tf32(v.z); t.w = f2tf32(v.w);
        ((uint4*)g_Wr)[i] = t;
    }

    int gidx = bid * 256 + tid;
    if (gidx < MAX_PAD) g_sorted[gidx] = -1;
    if (gidx < MAX_CHK) g_chunk_expert[gidx] = -1;
    if (gidx < NEXP) { g_hist[gidx] = 0; g_cnt[gidx] = 0; }

    if (bid == 0) {
        __shared__ int bad;
        if (tid == 0) bad = 0;
        __syncthreads();
        int lbad = 0;
        for (int i = tid; i < 2048; i += 256) {     // 16KB window, safe either dtype
            long long v = sel64[i];
            if (v < 0 || v >= NEXP) lbad = 1;
        }
        if (lbad) atomicOr(&bad, 1);
        __syncthreads();
        if (tid == 0) g_is64 = bad ? 0 : 1;
    }
}

// ---------------------------------------------------------------------------
// K_hist (32 CTAs x 256): smem-privatized histogram -> 64 global atomics/CTA.
// ---------------------------------------------------------------------------
__global__ void hist_kernel(const long long* __restrict__ sel64) {
    __shared__ int h[NEXP];
    const int tid = threadIdx.x;
    if (tid < NEXP) h[tid] = 0;
    __syncthreads();
    const int is64 = g_is64;
    const int* sel32 = (const int*)sel64;
    int n = blockIdx.x * 256 + tid;
    int e = is64 ? (int)sel64[n] : sel32[n];
    atomicAdd(&h[e], 1);
    __syncthreads();
    if (tid < NEXP && h[tid]) atomicAdd(&g_hist[tid], h[tid]);
}

// ---------------------------------------------------------------------------
// K_scatter (32 CTAs x 256): redundant per-CTA scan of 64 bins (Hillis-Steele
// in smem), CTA 0 writes chunk map, all CTAs scatter nodes.
// ---------------------------------------------------------------------------
__global__ void scatter_kernel(const long long* __restrict__ sel64) {
    __shared__ int sc[NEXP];    // inclusive scan of padded counts
    __shared__ int offs[NEXP];  // exclusive
    const int tid = threadIdx.x;

    int v = 0;
    if (tid < NEXP) {
        v = (g_hist[tid] + NODES_PER_CHUNK - 1) & ~(NODES_PER_CHUNK - 1);
        sc[tid] = v;
    }
    __syncthreads();
#pragma unroll
    for (int d = 1; d < NEXP; d <<= 1) {
        int t = 0;
        if (tid < NEXP && tid >= d) t = sc[tid - d];
        __syncthreads();
        if (tid < NEXP) sc[tid] += t;
        __syncthreads();
    }
    if (tid < NEXP) offs[tid] = sc[tid] - v;
    __syncthreads();

    if (blockIdx.x == 0 && tid < NEXP) {
        int c0 = offs[tid] / NODES_PER_CHUNK;
        int c1 = sc[tid] / NODES_PER_CHUNK;
        for (int c = c0; c < c1; c++) g_chunk_expert[c] = tid;
    }

    const int is64 = g_is64;
    const int* sel32 = (const int*)sel64;
    int n = blockIdx.x * 256 + tid;
    int e = is64 ? (int)sel64[n] : sel32[n];
    int pos = offs[e] + atomicAdd(&g_cnt[e], 1);
    g_sorted[pos] = n;
}

// ---------------------------------------------------------------------------
// K_gemm: grouped GEMM, tf32 mma.sync + ldmatrix + 3-stage cp.async pipe.
// CTA 128(M) x 128(N) x 128(K in 4 tiles of 32). 8 warps, warp tile 32x64.
// ---------------------------------------------------------------------------
extern __shared__ char smem[];

__global__ __launch_bounds__(256, 2)
void grouped_gemm_kernel(const float* __restrict__ x,
                         float* __restrict__ out) {
    const int e = g_chunk_expert[blockIdx.x];
    if (e < 0) return;

    int* snode = (int*)(smem + SMEM_NODE);
    const int tid  = threadIdx.x;
    const int lane = tid & 31;
    const int warp = tid >> 5;
    const int warp_m = (warp & 3) * 32;
    const int warp_n = (warp >> 2) * 64;

    if (tid < NODES_PER_CHUNK)
        snode[tid] = g_sorted[blockIdx.x * NODES_PER_CHUNK + tid];
    __syncthreads();

    const uint32_t sbase = smem_u32(smem);

    // --- per-thread cp.async source/dest (4 chunks each for A and B) ---
    const float* xa[4];
    const float* wa[4];
    uint32_t da[4], db[4];
    int      asz[4];
    const float* Wre = g_Wr + (size_t)e * CH * CH;
#pragma unroll
    for (int i = 0; i < 4; i++) {
        int id  = tid + i * 256;
        int row = id >> 3;
        int cq  = id & 7;
        int node = snode[row >> 3];
        asz[i] = (node >= 0) ? 16 : 0;
        if (node < 0) node = 0;
        xa[i] = x + ((size_t)(row & 7) * N_NODES + node) * CH + cq * 4;
        wa[i] = Wre + (size_t)row * CH + cq * 4;
        da[i] = sbase + (uint32_t)row * ROW_BYTES + cq * 16;
        db[i] = sbase + (uint32_t)(128 * ROW_BYTES) + (uint32_t)row * ROW_BYTES + cq * 16;
    }

    // --- ldmatrix base addresses (stage 0) ---
    uint32_t a_addr[2], b_addr[4];
    {
        int arow  = warp_m + (lane & 15);
        int abyte = (lane >> 4) * 16;
#pragma unroll
        for (int mt = 0; mt < 2; mt++)
            a_addr[mt] = sbase + (uint32_t)(arow + mt * 16) * ROW_BYTES + abyte;

        int brow  = warp_n + ((lane >> 4) << 3) + (lane & 7);
        int bbyte = ((lane >> 3) & 1) * 16;
#pragma unroll
        for (int p = 0; p < 4; p++)
            b_addr[p] = sbase + (uint32_t)(128 * ROW_BYTES)
                      + (uint32_t)(brow + p * 16) * ROW_BYTES + bbyte;
    }

    float acc[2][8][4];
#pragma unroll
    for (int mt = 0; mt < 2; mt++)
#pragma unroll
        for (int nt = 0; nt < 8; nt++)
#pragma unroll
            for (int i = 0; i < 4; i++) acc[mt][nt][i] = 0.0f;

    // --- issue tiles 0 and 1 ---
#pragma unroll
    for (int t = 0; t < 2; t++) {
        uint32_t so = t * STAGE;
        int go = t * KT;
#pragma unroll
        for (int i = 0; i < 4; i++) {
            cp16(da[i] + so, xa[i] + go, asz[i]);
            cp16(db[i] + so, wa[i] + go, 16);
        }
        cp_commit();
    }

    // --- main loop: 4 k-tiles ---
#pragma unroll
    for (int k = 0; k < 4; k++) {
        if (k + 2 < 4) {
            uint32_t so = ((k + 2) % NSTAGES) * STAGE;
            int go = (k + 2) * KT;
#pragma unroll
            for (int i = 0; i < 4; i++) {
                cp16(da[i] + so, xa[i] + go, asz[i]);
                cp16(db[i] + so, wa[i] + go, 16);
            }
            cp_commit();
        }
        if (k <= 1)      cp_wait<2>();
        else if (k == 2) cp_wait<1>();
        else             cp_wait<0>();
        __syncthreads();

        const uint32_t so = (k % NSTAGES) * STAGE;
#pragma unroll
        for (int ks = 0; ks < 4; ks++) {
            uint32_t a[2][4], b[4][4];
#pragma unroll
            for (int mt = 0; mt < 2; mt++)
                ldsm_x4(a[mt], a_addr[mt] + so + ks * 32);
#pragma unroll
            for (int p = 0; p < 4; p++)
                ldsm_x4(b[p], b_addr[p] + so + ks * 32);
#pragma unroll
            for (int mt = 0; mt < 2; mt++)
#pragma unroll
                for (int nt = 0; nt < 8; nt++)
                    mma_tf32(acc[mt][nt], a[mt], &b[nt >> 1][(nt & 1) * 2]);
        }
        __syncthreads();
    }

    // ---- epilogue: direct scattered stores ----
    const int g = lane >> 2;
    const int c = lane & 3;
#pragma unroll
    for (int mt = 0; mt < 2; mt++) {
#pragma unroll
        for (int half = 0; half < 2; half++) {
            int r = warp_m + mt * 16 + g + half * 8;
            int node = snode[r >> 3];
            if (node < 0) continue;
            float* o = out + ((size_t)(r & 7) * N_NODES + node) * CH + warp_n;
#pragma unroll
            for (int nt = 0; nt < 8; nt++) {
                float2 v2 = make_float2(acc[mt][nt][half * 2],
                                        acc[mt][nt][half * 2 + 1]);
                *(float2*)(o + nt * 8 + c * 2) = v2;
            }
        }
    }
}

// ---------------------------------------------------------------------------
extern "C" void kernel_launch(void* const* d_in, const int* in_sizes, int n_in,
                              void* d_out, int out_size) {
    const float*     x   = (const float*)d_in[0];
    const long long* sel = (const long long*)d_in[1];
    const float*     W   = (const float*)d_in[2];
    float*           out = (float*)d_out;

    static bool attr_set = false;
    if (!attr_set) {
        cudaFuncSetAttribute(grouped_gemm_kernel,
                             cudaFuncAttributeMaxDynamicSharedMemorySize,
                             SMEM_TOTAL);
        attr_set = true;
    }

    pre_kernel<<<128, 256>>>(W, sel);
    hist_kernel<<<32, 256>>>(sel);
    scatter_kernel<<<32, 256>>>(sel);
    grouped_gemm_kernel<<<MAX_CHK, 256, SMEM_TOTAL>>>(x, out);
}